// round 17
// baseline (speedup 1.0000x reference)
#include <cuda_runtime.h>
#include <cstdint>

// Fixed problem shape
#define BATCH 8
#define CDIM  64
#define NPTS  4096
#define KNN   20
#define TM    128        // targets per CTA == threads per CTA
#define NB    64         // candidates per block
#define NSPLIT 4
#define QN    (NPTS / NSPLIT)     // 1024 candidates per part
#define NBLK  (QN / NB)           // 16 blocks
#define CAP   10                  // buffer slots (trigger cnt>2, <=8 appends)
#define DSTR  65                  // sD row stride in floats (bank-conflict-free)

// Dynamic smem layout (bytes):
//   s_top [KNN][TM] u64   20480
//   s_buf [CAP][TM] u64   10240
//   sA    [CDIM][TM] f32  32768   (targets, permuted order)
//   sB    [CDIM][NB] f32  16384   (candidates, channel-major)
//   sD    [TM][DSTR] f32  33280   (distance block)
//   s_sqt [TM] f32          512
//   s_csq [NB] f32          256
#define SMEM_TOTAL (((KNN + CAP) * TM) * 8 + \
                    (CDIM * TM + CDIM * NB + TM * DSTR + TM + NB) * 4)

// Cross-kernel scratch (device globals; no allocations).
__device__ float g_csq[BATCH * NPTS];
__device__ unsigned long long g_part[NSPLIT][KNN][BATCH * NPTS];

__device__ __forceinline__ void cp_async16(const float* smem_dst, const float* gmem_src) {
    uint32_t s = (uint32_t)__cvta_generic_to_shared(smem_dst);
    asm volatile("cp.async.ca.shared.global [%0], [%1], 16;" :: "r"(s), "l"(gmem_src));
}
#define CP_COMMIT() asm volatile("cp.async.commit_group;" ::: "memory")
#define CP_WAIT0()  asm volatile("cp.async.wait_group 0;" ::: "memory")

// ---------------------------------------------------------------------------
// Prologue: g_csq[b][n] = sum_c x[b][c][n]^2, ascending-c sequential FMA —
// bit-identical to every passing round's norms.
// ---------------------------------------------------------------------------
__global__ void __launch_bounds__(256) sq_all(const float* __restrict__ x) {
    int idx = blockIdx.x * 256 + threadIdx.x;   // 0 .. B*N-1
    int b = idx >> 12;
    int n = idx & (NPTS - 1);
    const float* xb = x + b * CDIM * NPTS;
    float s = 0.f;
#pragma unroll
    for (int c = 0; c < CDIM; c++) {
        float v = xb[c * NPTS + n];             // coalesced
        s = fmaf(v, v, s);
    }
    g_csq[idx] = s;
}

// ---------------------------------------------------------------------------
// Kernel 1: register-blocked 8x8 GEMM per thread over 64-candidate blocks,
// epilogue writes d2 to an smem block, then a scan phase (thread t = target t)
// runs the EXACT verified top-K code (packed u64 keys = exact lax.top_k order;
// threshold + deferred buffer merge; branchless append).
// Per-(i,j) distance arithmetic bit-identical to all passing rounds:
//   dot: ascending-c fmaf chain in its own accumulator;
//   d2 = fma(dot, -2, sqt + csq).
// ---------------------------------------------------------------------------
__global__ void __launch_bounds__(TM) knn_part(const float* __restrict__ x) {
    extern __shared__ __align__(16) char smem_raw[];
    unsigned long long* s_top = (unsigned long long*)smem_raw;      // [KNN][TM]
    unsigned long long* s_buf = s_top + KNN * TM;                    // [CAP][TM]
    float* sA    = (float*)(s_buf + CAP * TM);                       // [CDIM][TM]
    float* sB    = sA + CDIM * TM;                                   // [CDIM][NB]
    float* sD    = sB + CDIM * NB;                                   // [TM][DSTR]
    float* s_sqt = sD + TM * DSTR;                                   // [TM]
    float* s_csq = s_sqt + TM;                                       // [NB]

    const int b    = blockIdx.y;
    const int part = blockIdx.z;
    const int tid  = threadIdx.x;
    const int tgt0 = blockIdx.x * TM;
    const float* xb = x + b * CDIM * NPTS;
    const float* cq = g_csq + b * NPTS;
    const int jbeg = part * QN;
    const int tx  = tid & 7;        // candidate group 0..7
    const int ty  = tid >> 3;       // target group 0..15
    const int tx8 = tx * 8;

    // --- One-time: stage A tile (permuted target order) + sqt. ---
    // Target g lives at sA[c][ (g%16)*8 + g/16 ], so thread (ty) reads its 8
    // targets {ty+16i} as two LDS.128 at sA[c][ty*8 .. ty*8+8).
    for (int e = 0; e < CDIM; e++) {           // 64 elements per thread
        int f = e * TM + tid;
        int c = f >> 7;                        // channel
        int g = f & 127;                       // target within CTA (coalesced)
        sA[c * TM + ((g & 15) * 8 + (g >> 4))] = xb[c * NPTS + tgt0 + g];
    }
    s_sqt[tid] = cq[tgt0 + tid];

    // Top-K init (exact code from the passing rounds).
#pragma unroll
    for (int k = 0; k < KNN; k++) s_top[k * TM + tid] = ~0ull;
    unsigned long long thresh = ~0ull;
    int cnt = 0;

    // Stage one candidate block (64 cands x 64 ch + csq) via cp.async.
    auto stageB = [&](int j0) {
#pragma unroll
        for (int k = 0; k < 8; k++) {
            int id  = tid * 8 + k;             // 0..1023 chunk id
            int c   = id >> 4;
            int off = (id & 15) * 4;
            cp_async16(sB + c * NB + off, xb + c * NPTS + j0 + off);
        }
        if (tid < 16)
            cp_async16(s_csq + tid * 4, cq + j0 + tid * 4);
        CP_COMMIT();
    };

    stageB(jbeg);                              // preload block 0
    __syncthreads();                           // sA/s_sqt/s_top visible

    for (int blk = 0; blk < NBLK; blk++) {
        const int j0 = jbeg + blk * NB;
        CP_WAIT0();
        __syncthreads();                       // sB ready; prior scan done

        // ---- GEMM: 8 targets x 8 candidates per thread ----
        float acc[8][8];
#pragma unroll
        for (int i = 0; i < 8; i++)
#pragma unroll
            for (int j = 0; j < 8; j++) acc[i][j] = 0.f;

#pragma unroll 8
        for (int c = 0; c < CDIM; c++) {
            float4 a0 = *(const float4*)(sA + c * TM + ty * 8);
            float4 a1 = *(const float4*)(sA + c * TM + ty * 8 + 4);
            float4 b0 = *(const float4*)(sB + c * NB + tx8);
            float4 b1 = *(const float4*)(sB + c * NB + tx8 + 4);
            float av[8] = {a0.x, a0.y, a0.z, a0.w, a1.x, a1.y, a1.z, a1.w};
            float bv[8] = {b0.x, b0.y, b0.z, b0.w, b1.x, b1.y, b1.z, b1.w};
#pragma unroll
            for (int i = 0; i < 8; i++)
#pragma unroll
                for (int j = 0; j < 8; j++)
                    acc[i][j] = fmaf(av[i], bv[j], acc[i][j]);
        }

        // ---- Epilogue: d2 = fma(dot, -2, sqt + csq) -> sD (conflict-free) ----
#pragma unroll
        for (int i = 0; i < 8; i++) {
            int g = ty + (i << 4);             // absolute target row (0..127)
            float sq_i = s_sqt[g];
#pragma unroll
            for (int j = 0; j < 8; j++) {
                float ts = sq_i + s_csq[tx8 + j];
                float d  = fmaf(acc[i][j], -2.0f, ts);   // one final rounding
                sD[g * DSTR + tx8 + j] = d;
            }
        }
        __syncthreads();                       // sD complete; sB consumed

        if (blk + 1 < NBLK) stageB(j0 + NB);   // overlaps the scan below

        // ---- Scan: thread t owns target t; EXACT verified top-K code ----
        const int tgt = tgt0 + tid;
        const float* drow = sD + tid * DSTR;   // stride 65: conflict-free
        for (int jj = 0; jj < NB; jj += 8) {
#pragma unroll
            for (int u = 0; u < 8; u++) {
                int   j = j0 + jj + u;
                float d = drow[jj + u];
                unsigned long long key =
                    ((unsigned long long)__float_as_uint(d) << 32) |
                    (unsigned int)j;
                // Branchless append (R14-proven).
                s_buf[cnt * TM + tid] = key;
                cnt += (int)((j != tgt) & (key < thresh));
            }
            // Deferred warp-wide merge; carry<=2 + <=8 appends <= CAP.
            if (__any_sync(0xffffffffu, cnt > 2)) {
                for (int i2 = 0; i2 < cnt; i2++) {
                    unsigned long long kv = s_buf[i2 * TM + tid];
                    if (kv < s_top[(KNN - 1) * TM + tid]) {
                        int k = KNN - 1;
                        while (k > 0 && s_top[(k - 1) * TM + tid] > kv) {
                            s_top[k * TM + tid] = s_top[(k - 1) * TM + tid];
                            k--;
                        }
                        s_top[k * TM + tid] = kv;
                    }
                }
                cnt = 0;
                thresh = s_top[(KNN - 1) * TM + tid];
            }
        }
        // loop-top CP_WAIT0+sync orders scan reads before next sD overwrite
    }

    for (int i2 = 0; i2 < cnt; i2++) {         // leftovers
        unsigned long long kv = s_buf[i2 * TM + tid];
        if (kv < s_top[(KNN - 1) * TM + tid]) {
            int k = KNN - 1;
            while (k > 0 && s_top[(k - 1) * TM + tid] > kv) {
                s_top[k * TM + tid] = s_top[(k - 1) * TM + tid];
                k--;
            }
            s_top[k * TM + tid] = kv;
        }
    }

    // Write sorted partial top-20 (coalesced in target index).
    const int col = b * NPTS + tgt0 + tid;
#pragma unroll
    for (int p = 0; p < KNN; p++)
        g_part[part][p][col] = s_top[p * TM + tid];
}

// ---------------------------------------------------------------------------
// Kernel 2: exact 4-way tournament merge (verbatim from passing round 9).
// Keys are globally unique (index embedded) -> u64 order is total & exact.
// ---------------------------------------------------------------------------
__global__ void __launch_bounds__(256) knn_merge(float* __restrict__ out) {
    const int idx = blockIdx.x * 256 + threadIdx.x;     // 0 .. B*N-1
    const int b = idx >> 12;                            // NPTS = 4096
    const int n = idx & (NPTS - 1);
    const int base0 = ((0 * BATCH + b) * NPTS + n) * KNN;
    const int base1 = ((1 * BATCH + b) * NPTS + n) * KNN;
    const float ftgt = (float)n;

    int i0 = 0, i1 = 0, i2 = 0, i3 = 0;
#pragma unroll
    for (int p = 0; p < KNN; p++) {
        unsigned long long v0 = g_part[0][i0][idx];
        unsigned long long v1 = g_part[1][i1][idx];
        unsigned long long v2 = g_part[2][i2][idx];
        unsigned long long v3 = g_part[3][i3][idx];
        bool l01 = v0 <= v1; unsigned long long m01 = l01 ? v0 : v1;
        bool l23 = v2 <= v3; unsigned long long m23 = l23 ? v2 : v3;
        bool lf  = m01 <= m23;
        unsigned long long m = lf ? m01 : m23;
        i0 += ( lf &&  l01) ? 1 : 0;
        i1 += ( lf && !l01) ? 1 : 0;
        i2 += (!lf &&  l23) ? 1 : 0;
        i3 += (!lf && !l23) ? 1 : 0;
        out[base0 + p] = (float)(int)(unsigned int)(m & 0xffffffffu);
        out[base1 + p] = ftgt;
    }
}

// ---------------------------------------------------------------------------
extern "C" void kernel_launch(void* const* d_in, const int* in_sizes, int n_in,
                              void* d_out, int out_size) {
    (void)in_sizes; (void)n_in; (void)out_size;
    const float* x = (const float*)d_in[0];
    float* out = (float*)d_out;

    // Opt-in to >48KB dynamic smem (idempotent, deterministic, no allocation).
    cudaFuncSetAttribute(knn_part,
                         cudaFuncAttributeMaxDynamicSharedMemorySize,
                         SMEM_TOTAL);

    sq_all<<<(BATCH * NPTS) / 256, 256>>>(x);
    dim3 grid(NPTS / TM, BATCH, NSPLIT);        // 32 x 8 x 4 = 1024 CTAs
    knn_part<<<grid, TM, SMEM_TOTAL>>>(x);
    knn_merge<<<(BATCH * NPTS) / 256, 256>>>(out);
}